// round 1
// baseline (speedup 1.0000x reference)
#include <cuda_runtime.h>
#include <cstdint>

#define N_NODES 50000
#define N_EDGES 600000
#define DIM     128

// Scratch: aggregated (h[src] + rel_emb[type]) summed into destination nodes.
// 50000 * 128 floats = 25.6 MB. __device__ global (no allocations allowed).
__device__ float g_S[(size_t)N_NODES * DIM];

// ---------------------------------------------------------------------------
// Kernel 1: zero the scatter accumulator
// ---------------------------------------------------------------------------
__global__ void zero_S_kernel() {
    size_t i = (size_t)blockIdx.x * blockDim.x + threadIdx.x;
    size_t n4 = (size_t)N_NODES * DIM / 4;
    if (i < n4) {
        ((float4*)g_S)[i] = make_float4(0.f, 0.f, 0.f, 0.f);
    }
}

// ---------------------------------------------------------------------------
// Kernel 2: edge scatter.  One warp per edge.
//   S[dst] += h[src] + rel_emb[type]
// Each lane handles 4 consecutive floats (float4), one red.v4 per lane.
// ---------------------------------------------------------------------------
__global__ void __launch_bounds__(256) scatter_edges_kernel(
    const float* __restrict__ h,
    const float* __restrict__ rel_emb,
    const int*   __restrict__ edge_src,
    const int*   __restrict__ edge_dst,
    const int*   __restrict__ edge_type)
{
    int warp = (int)((blockIdx.x * (unsigned)blockDim.x + threadIdx.x) >> 5);
    int lane = threadIdx.x & 31;
    if (warp >= N_EDGES) return;

    int s = __ldg(edge_src  + warp);
    int d = __ldg(edge_dst  + warp);
    int t = __ldg(edge_type + warp);

    const float4 hv = *(const float4*)(h       + (size_t)s * DIM + lane * 4);
    const float4 rv = *(const float4*)(rel_emb + (size_t)t * DIM + lane * 4);

    float4 m;
    m.x = hv.x + rv.x;
    m.y = hv.y + rv.y;
    m.z = hv.z + rv.z;
    m.w = hv.w + rv.w;

    float* outp = g_S + (size_t)d * DIM + lane * 4;
    asm volatile("red.global.add.v4.f32 [%0], {%1, %2, %3, %4};"
                 :: "l"(outp), "f"(m.x), "f"(m.y), "f"(m.z), "f"(m.w)
                 : "memory");
}

// ---------------------------------------------------------------------------
// Kernel 3: fused epilogue GEMM.
//   out = relu( (norm .* S) @ W_neighbor + h @ loop_weight )
// Block: 256 threads, 64 rows/block.  Two passes over K=128 each, reusing one
// 64KB smem W buffer + 32KB A staging.  Per thread: 8 rows x 4 cols outputs.
// ---------------------------------------------------------------------------
#define TILE_R 64

__global__ void __launch_bounds__(256) fused_gemm_kernel(
    const float* __restrict__ h,
    const float* __restrict__ norm,
    const float* __restrict__ W_neighbor,
    const float* __restrict__ loop_weight,
    float* __restrict__ out)
{
    extern __shared__ float smem[];
    float* sW = smem;                 // DIM*DIM = 16384 floats (64KB)
    float* sA = smem + DIM * DIM;     // TILE_R*DIM = 8192 floats (32KB)

    const int tid  = threadIdx.x;
    const int warp = tid >> 5;
    const int lane = tid & 31;
    const int row0 = blockIdx.x * TILE_R;

    float4 acc[8];
#pragma unroll
    for (int i = 0; i < 8; i++) acc[i] = make_float4(0.f, 0.f, 0.f, 0.f);

    // ---------------- pass 1: (norm .* S) @ W_neighbor -------------------
    // stage W_neighbor
    {
        const float4* W4  = (const float4*)W_neighbor;
        float4*       sW4 = (float4*)sW;
        for (int i = tid; i < DIM * DIM / 4; i += 256) sW4[i] = W4[i];
    }
    // stage A = norm * S
    for (int i = tid; i < TILE_R * (DIM / 4); i += 256) {
        int r  = i / (DIM / 4);
        int c  = i % (DIM / 4);
        int gr = row0 + r;
        float4 v = make_float4(0.f, 0.f, 0.f, 0.f);
        if (gr < N_NODES) {
            float nm = __ldg(norm + gr);
            float4 sv = ((const float4*)(g_S + (size_t)gr * DIM))[c];
            v.x = sv.x * nm; v.y = sv.y * nm; v.z = sv.z * nm; v.w = sv.w * nm;
        }
        ((float4*)(sA + r * DIM))[c] = v;
    }
    __syncthreads();
    {
        const float* arow = sA + warp * 8 * DIM;
#pragma unroll 8
        for (int k = 0; k < DIM; k++) {
            float4 b = ((const float4*)(sW + k * DIM))[lane];
#pragma unroll
            for (int i = 0; i < 8; i++) {
                float a = arow[i * DIM + k];
                acc[i].x += a * b.x;
                acc[i].y += a * b.y;
                acc[i].z += a * b.z;
                acc[i].w += a * b.w;
            }
        }
    }
    __syncthreads();

    // ---------------- pass 2: h @ loop_weight ----------------------------
    {
        const float4* W4  = (const float4*)loop_weight;
        float4*       sW4 = (float4*)sW;
        for (int i = tid; i < DIM * DIM / 4; i += 256) sW4[i] = W4[i];
    }
    for (int i = tid; i < TILE_R * (DIM / 4); i += 256) {
        int r  = i / (DIM / 4);
        int c  = i % (DIM / 4);
        int gr = row0 + r;
        float4 v = make_float4(0.f, 0.f, 0.f, 0.f);
        if (gr < N_NODES) v = ((const float4*)(h + (size_t)gr * DIM))[c];
        ((float4*)(sA + r * DIM))[c] = v;
    }
    __syncthreads();
    {
        const float* arow = sA + warp * 8 * DIM;
#pragma unroll 8
        for (int k = 0; k < DIM; k++) {
            float4 b = ((const float4*)(sW + k * DIM))[lane];
#pragma unroll
            for (int i = 0; i < 8; i++) {
                float a = arow[i * DIM + k];
                acc[i].x += a * b.x;
                acc[i].y += a * b.y;
                acc[i].z += a * b.z;
                acc[i].w += a * b.w;
            }
        }
    }

    // ---------------- epilogue: relu + store -----------------------------
#pragma unroll
    for (int i = 0; i < 8; i++) {
        int gr = row0 + warp * 8 + i;
        if (gr < N_NODES) {
            float4 v = acc[i];
            v.x = fmaxf(v.x, 0.f);
            v.y = fmaxf(v.y, 0.f);
            v.z = fmaxf(v.z, 0.f);
            v.w = fmaxf(v.w, 0.f);
            ((float4*)(out + (size_t)gr * DIM))[lane] = v;
        }
    }
}

// ---------------------------------------------------------------------------
// Launcher
// ---------------------------------------------------------------------------
extern "C" void kernel_launch(void* const* d_in, const int* in_sizes, int n_in,
                              void* d_out, int out_size)
{
    (void)in_sizes; (void)n_in; (void)out_size;

    const float* h          = (const float*)d_in[0];
    const float* norm       = (const float*)d_in[1];
    const float* rel_emb    = (const float*)d_in[2];
    const float* W_neighbor = (const float*)d_in[3];
    const float* loop_w     = (const float*)d_in[4];
    const int*   edge_src   = (const int*)d_in[5];
    const int*   edge_dst   = (const int*)d_in[6];
    const int*   edge_type  = (const int*)d_in[7];
    float*       out        = (float*)d_out;

    // 1) zero scatter accumulator
    {
        int n4 = N_NODES * DIM / 4;
        zero_S_kernel<<<(n4 + 255) / 256, 256>>>();
    }

    // 2) edge scatter (one warp per edge)
    {
        long long total_threads = (long long)N_EDGES * 32;
        int blocks = (int)((total_threads + 255) / 256);
        scatter_edges_kernel<<<blocks, 256>>>(h, rel_emb, edge_src, edge_dst, edge_type);
    }

    // 3) fused epilogue GEMM
    {
        const int smem_bytes = (DIM * DIM + TILE_R * DIM) * (int)sizeof(float); // 96KB
        cudaFuncSetAttribute(fused_gemm_kernel,
                             cudaFuncAttributeMaxDynamicSharedMemorySize, smem_bytes);
        int blocks = (N_NODES + TILE_R - 1) / TILE_R;
        fused_gemm_kernel<<<blocks, 256, smem_bytes>>>(h, norm, W_neighbor, loop_w, out);
    }
}